// round 15
// baseline (speedup 1.0000x reference)
#include <cuda_runtime.h>
#include <cuda_fp16.h>
#include <math.h>
#include <stdint.h>

// Shapes: B=4, S=2048, H=2048, I=5504, E=8, R=16, top-2
#define M_ROWS  8192
#define I_DIM   5504
#define H_DIM   2048

#define BM 256
#define BN 128
#define BK 64                         // fp16: 64 elems = 128 bytes per row
#define NSTAGE 4
#define ABYTES (BM * 128)             // 32768
#define BBYTES (BN * 128)             // 16384
#define PAIRBYTES (ABYTES + BBYTES)   // 49152
#define AWORDS (ABYTES / 4)
#define PAIRWORDS (PAIRBYTES / 4)
#define DSMEM (NSTAGE * PAIRBYTES)    // 196608

// ---------------- scratch ----------------
__device__ __half g_h  [45088768];   // h = silu(gate)*up, fp16
__device__ float  g_up [45088768];   // up GEMM result, fp32
__device__ __half g_xh [16777216];   // fp16 x
__device__ __half g_wgh[11272192];
__device__ __half g_wuh[11272192];
__device__ __half g_wdh[11272192];
__device__ float  g_u  [8192*64];
__device__ float  g_v  [8192*32];
__device__ int    g_sel[8];

// ---------------- helpers ----------------
__device__ __forceinline__ uint32_t smem_u32(const void* p) {
    uint32_t a;
    asm("{ .reg .u64 t; cvta.to.shared.u64 t, %1; cvt.u32.u64 %0, t; }" : "=r"(a) : "l"(p));
    return a;
}
__device__ __forceinline__ uint32_t h2u(__half2 h) {
    return *reinterpret_cast<uint32_t*>(&h);
}
__device__ __forceinline__ void sts128(uint32_t a, uint32_t x, uint32_t y, uint32_t z, uint32_t w) {
    asm volatile("st.shared.v4.b32 [%0], {%1,%2,%3,%4};" :: "r"(a), "r"(x), "r"(y), "r"(z), "r"(w) : "memory");
}
__device__ __forceinline__ void cpasync16(uint32_t dst, const void* src) {
    asm volatile("cp.async.cg.shared.global [%0], [%1], 16;" :: "r"(dst), "l"(src) : "memory");
}
__device__ __forceinline__ void cp_commit() {
    asm volatile("cp.async.commit_group;" ::: "memory");
}
template<int N>
__device__ __forceinline__ void cp_wait() {
    asm volatile("cp.async.wait_group %0;" :: "n"(N) : "memory");
}
__device__ __forceinline__ void ldmatrix_x4(uint32_t& r0, uint32_t& r1, uint32_t& r2, uint32_t& r3,
                                            uint32_t addr) {
    asm volatile("ldmatrix.sync.aligned.m8n8.x4.shared.b16 {%0,%1,%2,%3}, [%4];"
        : "=r"(r0), "=r"(r1), "=r"(r2), "=r"(r3) : "r"(addr));
}
__device__ __forceinline__ void mma_fp16(float* c,
                                         uint32_t a0, uint32_t a1, uint32_t a2, uint32_t a3,
                                         uint32_t b0, uint32_t b1) {
    asm volatile(
        "mma.sync.aligned.m16n8k16.row.col.f32.f16.f16.f32 "
        "{%0,%1,%2,%3},{%4,%5,%6,%7},{%8,%9},{%0,%1,%2,%3};"
        : "+f"(c[0]), "+f"(c[1]), "+f"(c[2]), "+f"(c[3])
        : "r"(a0), "r"(a1), "r"(a2), "r"(a3), "r"(b0), "r"(b1));
}
__device__ __forceinline__ float silu(float x) {
    return x / (1.f + expf(-x));
}

// ---------------- fp32 -> fp16 pass (8 elems/thread) ----------------
__global__ void cvt_f2h_kernel(const float* __restrict__ in, __half* __restrict__ out, int n8)
{
    int i = blockIdx.x * blockDim.x + threadIdx.x;
    if (i >= n8) return;
    float4 v0 = reinterpret_cast<const float4*>(in)[2*i];
    float4 v1 = reinterpret_cast<const float4*>(in)[2*i+1];
    uint4 o;
    o.x = h2u(__floats2half2_rn(v0.x, v0.y));
    o.y = h2u(__floats2half2_rn(v0.z, v0.w));
    o.z = h2u(__floats2half2_rn(v1.x, v1.y));
    o.w = h2u(__floats2half2_rn(v1.z, v1.w));
    reinterpret_cast<uint4*>(out)[i] = o;
}

// ---------------- top-2 gating ----------------
__global__ void topk_kernel(const float* __restrict__ gv) {
    int b = threadIdx.x;
    if (b >= 4) return;
    const float* r = gv + b * 8;
    int i0 = 0; float v0 = r[0];
    #pragma unroll
    for (int e = 1; e < 8; e++) if (r[e] > v0) { v0 = r[e]; i0 = e; }
    int i1 = -1; float v1 = -3.4e38f;
    #pragma unroll
    for (int e = 0; e < 8; e++) if (e != i0 && r[e] > v1) { v1 = r[e]; i1 = e; }
    g_sel[2*b] = i0; g_sel[2*b+1] = i1;
}

// ---------------- U = X @ A_sel (32 cols: 2 experts x r=16) ----------------
template<typename T>
__global__ void lora_proj_kernel(const T* __restrict__ X,
                                 const float* __restrict__ A,
                                 int K, float* __restrict__ U,
                                 int ustride, int uoff)
{
    __shared__ float Xs[8][128];
    int tid = threadIdx.x;
    int col = tid & 31, lr = tid >> 5;
    int row0 = blockIdx.x * 8;
    int b = row0 >> 11;
    int e = g_sel[2*b + (col >> 4)];
    int r = col & 15;
    const float* Ap = A + (size_t)e * K * 16 + r;

    float acc = 0.f;
    for (int k0 = 0; k0 < K; k0 += 128) {
        int flat = tid * 4;
        int rr = flat >> 7, cc = flat & 127;
        #pragma unroll
        for (int t = 0; t < 4; t++)
            Xs[rr][cc + t] = (float)X[(size_t)(row0 + rr) * K + k0 + cc + t];
        __syncthreads();
        #pragma unroll 8
        for (int kk = 0; kk < 128; kk++)
            acc += Xs[lr][kk] * Ap[(size_t)(k0 + kk) * 16];
        __syncthreads();
    }
    U[(size_t)(row0 + lr) * ustride + uoff + col] = acc;
}

// ---------------- fp16 mma.sync GEMM, cp.async 4-stage, ldmatrix fragments ----------------
// C = A @ W^T + U @ (2*Bl_sel). A,W fp16 (pre-rounded). LoRA: zero-padded K-chunk.
// Up == nullptr -> write fp32 C; else write Ch = half(silu(acc)*Up).
__global__ void __launch_bounds__(256, 1)
gemm_mma_kernel(const __half* __restrict__ A, const __half* __restrict__ W,
                const float* __restrict__ U, int ustride, int uoff,
                const float* __restrict__ Bl,
                const float* __restrict__ Up,
                float* __restrict__ C, __half* __restrict__ Ch,
                int N, int K)
{
    extern __shared__ __align__(128) uint32_t smem_u[];
    uint32_t smem_base = smem_u32(smem_u);

    int tid  = threadIdx.x;
    int wid  = tid >> 5, lane = tid & 31;
    int g    = lane >> 2, tig = lane & 3;
    int warp_m = (wid >> 1) * 64;
    int warp_n = (wid & 1) * 64;
    int row0 = blockIdx.y * BM, col0 = blockIdx.x * BN;
    int bb   = row0 >> 11;
    int e0 = g_sel[2*bb], e1 = g_sel[2*bb+1];

    float acc[4][8][4];
    #pragma unroll
    for (int i = 0; i < 4; i++)
        #pragma unroll
        for (int j = 0; j < 8; j++)
            #pragma unroll
            for (int q = 0; q < 4; q++) acc[i][j][q] = 0.f;

    // loader: 8 threads/row, 16B (8 fp16) each
    int lr  = tid >> 3;                 // 0..31
    int seg = tid & 7;                  // 0..7
    uint32_t dstA[8], dstB[4];
    #pragma unroll
    for (int j = 0; j < 8; j++)
        dstA[j] = (uint32_t)((lr + 32*j) * 128 + 16 * (seg ^ (lr & 7)));
    #pragma unroll
    for (int j = 0; j < 4; j++)
        dstB[j] = (uint32_t)((lr + 32*j) * 128 + 16 * (seg ^ (lr & 7)));

    const __half* aptr = A + (size_t)(row0 + lr) * K + seg * 8;
    const __half* wptr = W + (size_t)(col0 + lr) * K + seg * 8;

    int nk = K >> 6;                    // 64-wide chunks
    int ntot = nk + 1;

    auto issue_chunk = [&](int i) {
        int buf = i & (NSTAGE - 1);
        uint32_t a_s = smem_base + (uint32_t)buf * PAIRBYTES;
        uint32_t b_s = a_s + ABYTES;
        if (i < nk) {
            const __half* ap = aptr + (i << 6);
            const __half* wp = wptr + (i << 6);
            #pragma unroll
            for (int j = 0; j < 8; j++)
                cpasync16(a_s + dstA[j], ap + (size_t)(32 * j) * K);
            #pragma unroll
            for (int j = 0; j < 4; j++)
                cpasync16(b_s + dstB[j], wp + (size_t)(32 * j) * K);
        } else {
            // LoRA chunk (rank 32, zero-padded to 64)
            if (seg < 4) {
                int cbase = seg * 8;
                #pragma unroll
                for (int j = 0; j < 8; j++) {
                    const float* us = U + (size_t)(row0 + lr + 32*j) * ustride + uoff + cbase;
                    float4 u0 = *reinterpret_cast<const float4*>(us);
                    float4 u1 = *reinterpret_cast<const float4*>(us + 4);
                    sts128(a_s + dstA[j],
                           h2u(__floats2half2_rn(u0.x, u0.y)), h2u(__floats2half2_rn(u0.z, u0.w)),
                           h2u(__floats2half2_rn(u1.x, u1.y)), h2u(__floats2half2_rn(u1.z, u1.w)));
                }
                int e = (seg < 2) ? e0 : e1;
                #pragma unroll
                for (int j = 0; j < 4; j++) {
                    int n = lr + 32*j;
                    float f[8];
                    #pragma unroll
                    for (int t = 0; t < 8; t++) {
                        int k = cbase + t;
                        f[t] = 2.0f * Bl[((size_t)(e * 16 + (k & 15))) * N + col0 + n];
                    }
                    sts128(b_s + dstB[j],
                           h2u(__floats2half2_rn(f[0], f[1])), h2u(__floats2half2_rn(f[2], f[3])),
                           h2u(__floats2half2_rn(f[4], f[5])), h2u(__floats2half2_rn(f[6], f[7])));
                }
            } else {
                #pragma unroll
                for (int j = 0; j < 8; j++) sts128(a_s + dstA[j], 0u, 0u, 0u, 0u);
                #pragma unroll
                for (int j = 0; j < 4; j++) sts128(b_s + dstB[j], 0u, 0u, 0u, 0u);
            }
        }
        cp_commit();
    };

    // prologue
    issue_chunk(0);
    issue_chunk(1);
    issue_chunk(2);

    // ---- ldmatrix lane geometry ----
    int lrow = lane & 7;
    int lmat = lane >> 3;               // 0..3
    // A x4: mat0 rows m0..+7 klo, mat1 rows +8..15 klo, mat2 rows m0..+7 khi, mat3 rows +8 khi
    uint32_t a_row[4];
    #pragma unroll
    for (int mt = 0; mt < 4; mt++)
        a_row[mt] = (uint32_t)(warp_m + mt * 16 + (lmat & 1) * 8 + lrow);
    int a_cadd = lmat >> 1;
    // B x4: mat0 n0..+7 klo (b0 of tile 2p), mat1 same rows khi (b1), mat2 rows +8 klo, mat3 +8 khi
    uint32_t b_row[4];
    #pragma unroll
    for (int p = 0; p < 4; p++)
        b_row[p] = (uint32_t)(warp_n + p * 16 + (lmat >> 1) * 8 + lrow);
    int b_cadd = lmat & 1;

    for (int i = 0; i < ntot; i++) {
        cp_wait<2>();
        __syncthreads();

        if (i + 3 < ntot) issue_chunk(i + 3);
        else cp_commit();

        int buf = i & (NSTAGE - 1);
        uint32_t a_sb = smem_base + (uint32_t)buf * PAIRBYTES;
        uint32_t b_sb = a_sb + ABYTES;

        #pragma unroll
        for (int ks = 0; ks < 4; ks++) {       // 4 x k16 per 64-chunk
            int ac = ks * 2 + a_cadd;
            int bc = ks * 2 + b_cadd;
            uint32_t af[4][4];
            #pragma unroll
            for (int mt = 0; mt < 4; mt++) {
                uint32_t addr = a_sb + a_row[mt] * 128u + 16u * (uint32_t)(ac ^ (a_row[mt] & 7));
                ldmatrix_x4(af[mt][0], af[mt][1], af[mt][2], af[mt][3], addr);
            }
            uint32_t b0[8], b1[8];
            #pragma unroll
            for (int p = 0; p < 4; p++) {
                uint32_t addr = b_sb + b_row[p] * 128u + 16u * (uint32_t)(bc ^ (b_row[p] & 7));
                ldmatrix_x4(b0[2*p], b1[2*p], b0[2*p+1], b1[2*p+1], addr);
            }
            #pragma unroll
            for (int mt = 0; mt < 4; mt++)
                #pragma unroll
                for (int nt = 0; nt < 8; nt++)
                    mma_fp16(acc[mt][nt], af[mt][0], af[mt][1], af[mt][2], af[mt][3],
                             b0[nt], b1[nt]);
        }
    }

    // ---- epilogue ----
    if (Up == nullptr) {
        #pragma unroll
        for (int mt = 0; mt < 4; mt++) {
            int m = row0 + warp_m + mt * 16 + g;
            #pragma unroll
            for (int nt = 0; nt < 8; nt++) {
                int n = col0 + warp_n + nt * 8 + tig * 2;
                float2* p0 = reinterpret_cast<float2*>(C + (size_t)m * N + n);
                float2* p1 = reinterpret_cast<float2*>(C + (size_t)(m + 8) * N + n);
                *p0 = make_float2(acc[mt][nt][0], acc[mt][nt][1]);
                *p1 = make_float2(acc[mt][nt][2], acc[mt][nt][3]);
            }
        }
    } else {
        // fused SwiGLU: h = fp16(silu(gate) * up)
        #pragma unroll
        for (int mt = 0; mt < 4; mt++) {
            int m = row0 + warp_m + mt * 16 + g;
            #pragma unroll
            for (int nt = 0; nt < 8; nt++) {
                int n = col0 + warp_n + nt * 8 + tig * 2;
                float2 up0 = *reinterpret_cast<const float2*>(Up + (size_t)m * N + n);
                float2 up1 = *reinterpret_cast<const float2*>(Up + (size_t)(m + 8) * N + n);
                uint32_t* p0 = reinterpret_cast<uint32_t*>(Ch + (size_t)m * N + n);
                uint32_t* p1 = reinterpret_cast<uint32_t*>(Ch + (size_t)(m + 8) * N + n);
                *p0 = h2u(__floats2half2_rn(silu(acc[mt][nt][0]) * up0.x,
                                            silu(acc[mt][nt][1]) * up0.y));
                *p1 = h2u(__floats2half2_rn(silu(acc[mt][nt][2]) * up1.x,
                                            silu(acc[mt][nt][3]) * up1.y));
            }
        }
    }
}

// ---------------- launch ----------------
extern "C" void kernel_launch(void* const* d_in, const int* in_sizes, int n_in,
                              void* d_out, int out_size)
{
    const float* x  = (const float*)d_in[0];
    const float* gv = (const float*)d_in[1];
    const float* Wg = (const float*)d_in[2];
    const float* Ag = (const float*)d_in[3];
    const float* Bg = (const float*)d_in[4];
    const float* Wu = (const float*)d_in[5];
    const float* Au = (const float*)d_in[6];
    const float* Bu = (const float*)d_in[7];
    const float* Wd = (const float*)d_in[8];
    const float* Ad = (const float*)d_in[9];
    const float* Bd = (const float*)d_in[10];
    float* out = (float*)d_out;

    float *up, *u, *v;
    __half *hbuf, *xh, *wgh, *wuh, *wdh;
    cudaGetSymbolAddress((void**)&hbuf, g_h);
    cudaGetSymbolAddress((void**)&up,   g_up);
    cudaGetSymbolAddress((void**)&u,    g_u);
    cudaGetSymbolAddress((void**)&v,    g_v);
    cudaGetSymbolAddress((void**)&xh,   g_xh);
    cudaGetSymbolAddress((void**)&wgh,  g_wgh);
    cudaGetSymbolAddress((void**)&wuh,  g_wuh);
    cudaGetSymbolAddress((void**)&wdh,  g_wdh);

    cudaFuncSetAttribute(gemm_mma_kernel, cudaFuncAttributeMaxDynamicSharedMemorySize, DSMEM);

    topk_kernel<<<1, 4>>>(gv);

    // fp32 -> fp16 operand conversion
    cvt_f2h_kernel<<<(16777216/8 + 255)/256, 256>>>(x,  xh,  16777216/8);
    cvt_f2h_kernel<<<(11272192/8 + 255)/256, 256>>>(Wg, wgh, 11272192/8);
    cvt_f2h_kernel<<<(11272192/8 + 255)/256, 256>>>(Wu, wuh, 11272192/8);
    cvt_f2h_kernel<<<(11272192/8 + 255)/256, 256>>>(Wd, wdh, 11272192/8);

    lora_proj_kernel<float><<<1024, 256>>>(x, Ag, H_DIM, u, 64, 0);
    lora_proj_kernel<float><<<1024, 256>>>(x, Au, H_DIM, u, 64, 32);

    // up GEMM (fp32 out), then gate GEMM with fused SwiGLU -> h (fp16)
    gemm_mma_kernel<<<dim3(I_DIM/BN, M_ROWS/BM), 256, DSMEM>>>(
        xh, wuh, u, 64, 32, Bu, nullptr, up, nullptr, I_DIM, H_DIM);
    gemm_mma_kernel<<<dim3(I_DIM/BN, M_ROWS/BM), 256, DSMEM>>>(
        xh, wgh, u, 64, 0,  Bg, up, nullptr, hbuf, I_DIM, H_DIM);

    lora_proj_kernel<__half><<<1024, 256>>>(hbuf, Ad, I_DIM, v, 32, 0);

    gemm_mma_kernel<<<dim3(H_DIM/BN, M_ROWS/BM), 256, DSMEM>>>(
        hbuf, wdh, v, 32, 0, Bd, nullptr, out, nullptr, H_DIM, I_DIM);
}